// round 1
// baseline (speedup 1.0000x reference)
#include <cuda_runtime.h>
#include <cuda_fp16.h>
#include <cstdint>

// Problem constants (fixed by the reference)
#define NPTS   100000
#define C_IMG  512
#define C_PT   256
#define BSZ    8
#define IMH    48
#define IMW    160

#define TM     64          // points per block in fused kernel
#define PITCH_S 65         // smem pitch for S[512][64] (pad to kill bank conflicts)
#define PITCH_W 260        // smem pitch for W chunk [32][256]
#define SMEM_BYTES ((512*PITCH_S + 32*PITCH_W) * 4)

// ---------------- scratch (device globals: no allocation allowed) -------------
__device__ __half g_imgT[BSZ * IMH * IMW * C_IMG];   // (B,H,W,C) fp16, ~63 MB
__device__ float  g_M[BSZ * 12];                     // combined 3x4 projection per batch
__device__ float4 g_w[NPTS];                         // 4 bilinear weights (valid-masked)
__device__ int4   g_off[NPTS];                       // 4 corner element offsets into g_imgT

// ---------------- packed f32x2 helpers ---------------------------------------
#define PACKF2(out, lo, hi) \
    asm("mov.b64 %0, {%1, %2};" : "=l"(out) : "f"(lo), "f"(hi))
#define UNPACKF2(lo, hi, in) \
    asm("mov.b64 {%0, %1}, %2;" : "=f"(lo), "=f"(hi) : "l"(in))
#define FMA2(d, a, b, c) \
    asm("fma.rn.f32x2 %0, %1, %2, %3;" : "=l"(d) : "l"(a), "l"(b), "l"(c))

// ================== kernel 0: build combined projection matrices =============
__global__ void build_mats_kernel(const float* __restrict__ P2,
                                  const float* __restrict__ R0,
                                  const float* __restrict__ Tr) {
    int b = threadIdx.x;
    if (b >= BSZ) return;
    float A[16];
    // A = R0[b] @ Tr[b]   (4x4)
    for (int i = 0; i < 4; ++i)
        for (int j = 0; j < 4; ++j) {
            float s = 0.f;
            for (int k = 0; k < 4; ++k)
                s += R0[b*16 + i*4 + k] * Tr[b*16 + k*4 + j];
            A[i*4 + j] = s;
        }
    // M = P2[b] @ A   (3x4)
    for (int i = 0; i < 3; ++i)
        for (int j = 0; j < 4; ++j) {
            float s = 0.f;
            for (int k = 0; k < 4; ++k)
                s += P2[b*12 + i*4 + k] * A[k*4 + j];
            g_M[b*12 + i*4 + j] = s;
        }
}

// ================== kernel 1: transpose img_feat (B,C,H,W)->(B,H,W,C) fp16 ===
// grid: (W/32, C/32, B*H), block (32,8)
__global__ void transpose_img_kernel(const float* __restrict__ img) {
    __shared__ float tile[32][33];
    int bz = blockIdx.z;
    int b = bz / IMH, y = bz % IMH;
    int x0 = blockIdx.x * 32, c0 = blockIdx.y * 32;
    int tx = threadIdx.x, ty = threadIdx.y;
    #pragma unroll
    for (int j = 0; j < 4; ++j) {
        int c = c0 + ty + j * 8;
        tile[ty + j * 8][tx] =
            img[((size_t)(b * C_IMG + c) * IMH + y) * IMW + x0 + tx];
    }
    __syncthreads();
    #pragma unroll
    for (int j = 0; j < 4; ++j) {
        int x = x0 + ty + j * 8;
        g_imgT[((size_t)((b * IMH + y) * IMW + x)) * C_IMG + c0 + tx] =
            __float2half(tile[tx][ty + j * 8]);
    }
}

// ================== kernel 2: per-point projection -> weights + offsets ======
__global__ void project_kernel(const float* __restrict__ centers,
                               const int* __restrict__ bidx) {
    int tid = blockIdx.x * blockDim.x + threadIdx.x;
    if (tid >= NPTS) return;
    int b = bidx[tid];
    const float* M = g_M + b * 12;
    float x = centers[tid * 3 + 0];
    float y = centers[tid * 3 + 1];
    float z = centers[tid * 3 + 2];
    float u  = M[0] * x + M[1] * y + M[2]  * z + M[3];
    float v  = M[4] * x + M[5] * y + M[6]  * z + M[7];
    float zc = M[8] * x + M[9] * y + M[10] * z + M[11];
    float depth = fmaxf(zc, 1e-5f);
    float uu = u / depth;
    float vv = v / depth;
    bool valid = (zc > 0.f) && (uu >= 0.f) && (uu < (float)IMW) &&
                 (vv >= 0.f) && (vv < (float)IMH);
    float x0f = floorf(uu), y0f = floorf(vv);
    float wx1 = uu - x0f, wx0 = 1.f - wx1;
    float wy1 = vv - y0f, wy0 = 1.f - wy1;
    int xi0 = (int)x0f, yi0 = (int)y0f;

    float4 wout;
    int4 oout;
    // corner order: (x0,y0) (x0+1,y0) (x0,y0+1) (x0+1,y0+1)
    int   xs[4] = {xi0, xi0 + 1, xi0, xi0 + 1};
    int   ys[4] = {yi0, yi0, yi0 + 1, yi0 + 1};
    float ws[4] = {wx0 * wy0, wx1 * wy0, wx0 * wy1, wx1 * wy1};
    float wo[4];
    int   oo[4];
    #pragma unroll
    for (int j = 0; j < 4; ++j) {
        bool inb = (xs[j] >= 0) && (xs[j] <= IMW - 1) &&
                   (ys[j] >= 0) && (ys[j] <= IMH - 1);
        int xc = min(max(xs[j], 0), IMW - 1);
        int yc = min(max(ys[j], 0), IMH - 1);
        oo[j] = ((b * IMH + yc) * IMW + xc) * C_IMG;
        wo[j] = (valid && inb) ? ws[j] : 0.f;   // select, never multiply (NaN safety)
    }
    wout.x = wo[0]; wout.y = wo[1]; wout.z = wo[2]; wout.w = wo[3];
    oout.x = oo[0]; oout.y = oo[1]; oout.z = oo[2]; oout.w = oo[3];
    g_w[tid] = wout;
    g_off[tid] = oout;
}

// ================== kernel 3: fused gather + GEMM + residual =================
// Block: 256 threads, TM=64 points, all 256 output channels.
// Per thread: 8 points x 8 channels accumulated as 32 packed f32x2 FMAs/k.
__global__ void __launch_bounds__(256, 1)
fuse_kernel(const float* __restrict__ point_feat,
            const float* __restrict__ align_w,
            const float* __restrict__ align_b,
            float* __restrict__ out) {
    extern __shared__ float sm[];
    float* S  = sm;                  // [512][PITCH_S]  sampled features (k-major)
    float* Wt = sm + 512 * PITCH_S;  // [32][PITCH_W]   W chunk, transposed

    const int t   = threadIdx.x;
    const int blk = blockIdx.x;
    const int p0  = blk * TM;

    // ---- gather phase: fill S[k][p_local] -----------------------------------
    const __half2* imgT2 = (const __half2*)g_imgT;
    const int k2 = t;  // each thread owns channel pair 2t,2t+1
    for (int it = 0; it < TM; ++it) {
        int p = p0 + it;
        float4 w = make_float4(0.f, 0.f, 0.f, 0.f);
        int4 off = make_int4(0, 0, 0, 0);
        if (p < NPTS) { w = g_w[p]; off = g_off[p]; }
        __half2 h0 = imgT2[(off.x >> 1) + k2];
        __half2 h1 = imgT2[(off.y >> 1) + k2];
        __half2 h2 = imgT2[(off.z >> 1) + k2];
        __half2 h3 = imgT2[(off.w >> 1) + k2];
        float2 f0 = __half22float2(h0);
        float2 f1 = __half22float2(h1);
        float2 f2 = __half22float2(h2);
        float2 f3 = __half22float2(h3);
        float se = w.x * f0.x + w.y * f1.x + w.z * f2.x + w.w * f3.x;
        float so = w.x * f0.y + w.y * f1.y + w.z * f2.y + w.w * f3.y;
        S[(2 * k2) * PITCH_S + it]     = se;
        S[(2 * k2 + 1) * PITCH_S + it] = so;
    }

    // ---- GEMM phase ----------------------------------------------------------
    const int tc = t & 31;       // channel group 0..31
    const int tr = t >> 5;       // point group 0..7
    const int c0 = tc * 4;       // channels [c0..c0+3] and [128+c0..128+c0+3]
    const int prow = tr * 8;     // points   [prow..prow+7] (local)

    unsigned long long acc[8][4];
    #pragma unroll
    for (int i = 0; i < 8; ++i)
        #pragma unroll
        for (int j = 0; j < 4; ++j) acc[i][j] = 0ULL;

    for (int ch = 0; ch < 16; ++ch) {
        __syncthreads();  // previous chunk fully consumed (also covers gather)
        // load W chunk [32k][256c] transposed into Wt; coalesced along k
        const int cload = (t >> 3);         // 0..31 (channel within pass)
        const int kl    = (t & 7) * 4;      // k within chunk, float4-aligned
        #pragma unroll
        for (int r = 0; r < 8; ++r) {
            int c = r * 32 + cload;
            float4 v = *(const float4*)&align_w[(size_t)c * C_IMG + ch * 32 + kl];
            Wt[(kl + 0) * PITCH_W + c] = v.x;
            Wt[(kl + 1) * PITCH_W + c] = v.y;
            Wt[(kl + 2) * PITCH_W + c] = v.z;
            Wt[(kl + 3) * PITCH_W + c] = v.w;
        }
        __syncthreads();

        #pragma unroll 8
        for (int kk = 0; kk < 32; ++kk) {
            float4 wa = *(const float4*)&Wt[kk * PITCH_W + c0];
            float4 wb = *(const float4*)&Wt[kk * PITCH_W + 128 + c0];
            unsigned long long w01, w23, w45, w67;
            PACKF2(w01, wa.x, wa.y);
            PACKF2(w23, wa.z, wa.w);
            PACKF2(w45, wb.x, wb.y);
            PACKF2(w67, wb.z, wb.w);
            const float* Srow = &S[(ch * 32 + kk) * PITCH_S + prow];
            #pragma unroll
            for (int i = 0; i < 8; ++i) {
                float s = Srow[i];
                unsigned long long s2;
                PACKF2(s2, s, s);
                FMA2(acc[i][0], s2, w01, acc[i][0]);
                FMA2(acc[i][1], s2, w23, acc[i][1]);
                FMA2(acc[i][2], s2, w45, acc[i][2]);
                FMA2(acc[i][3], s2, w67, acc[i][3]);
            }
        }
    }

    // ---- epilogue: out = point_feat + bias + acc -----------------------------
    float4 b0 = *(const float4*)&align_b[c0];
    float4 b1 = *(const float4*)&align_b[128 + c0];
    #pragma unroll
    for (int i = 0; i < 8; ++i) {
        int p = p0 + prow + i;
        if (p >= NPTS) continue;
        float e0, e1, e2, e3, e4, e5, e6, e7;
        UNPACKF2(e0, e1, acc[i][0]);
        UNPACKF2(e2, e3, acc[i][1]);
        UNPACKF2(e4, e5, acc[i][2]);
        UNPACKF2(e6, e7, acc[i][3]);
        const float4 pf0 = *(const float4*)&point_feat[(size_t)p * C_PT + c0];
        const float4 pf1 = *(const float4*)&point_feat[(size_t)p * C_PT + 128 + c0];
        float4 o0 = make_float4(pf0.x + b0.x + e0, pf0.y + b0.y + e1,
                                pf0.z + b0.z + e2, pf0.w + b0.w + e3);
        float4 o1 = make_float4(pf1.x + b1.x + e4, pf1.y + b1.y + e5,
                                pf1.z + b1.z + e6, pf1.w + b1.w + e7);
        *(float4*)&out[(size_t)p * C_PT + c0]       = o0;
        *(float4*)&out[(size_t)p * C_PT + 128 + c0] = o1;
    }
}

// ================== launcher ==================================================
extern "C" void kernel_launch(void* const* d_in, const int* in_sizes, int n_in,
                              void* d_out, int out_size) {
    const float* point_feat = (const float*)d_in[0];
    const float* centers    = (const float*)d_in[1];
    const float* img        = (const float*)d_in[2];
    const float* P2         = (const float*)d_in[3];
    const float* R0         = (const float*)d_in[4];
    const float* Tr         = (const float*)d_in[5];
    const float* align_w    = (const float*)d_in[6];
    const float* align_b    = (const float*)d_in[7];
    const int*   bidx       = (const int*)d_in[8];
    float* out = (float*)d_out;

    build_mats_kernel<<<1, 32>>>(P2, R0, Tr);
    transpose_img_kernel<<<dim3(IMW / 32, C_IMG / 32, BSZ * IMH), dim3(32, 8)>>>(img);
    project_kernel<<<(NPTS + 255) / 256, 256>>>(centers, bidx);

    cudaFuncSetAttribute(fuse_kernel,
                         cudaFuncAttributeMaxDynamicSharedMemorySize, SMEM_BYTES);
    fuse_kernel<<<(NPTS + TM - 1) / TM, 256, SMEM_BYTES>>>(
        point_feat, align_w, align_b, out);
}

// round 3
// speedup vs baseline: 3.1943x; 3.1943x over previous
#include <cuda_runtime.h>
#include <cuda_fp16.h>
#include <cuda_bf16.h>
#include <cstdint>

// Problem constants (fixed by the reference)
#define NPTS   100000
#define C_IMG  512
#define C_PT   256
#define BSZ    8
#define IMH    48
#define IMW    160

#define TM     128               // points per CTA (MMA M)
#define NCHUNK 8                 // K chunks of 64
#define W_CHUNK_BYTES 32768      // 256 n-rows x 64 k x 2B (swizzled)
#define S_BYTES (128 * 1024)     // 128 rows x 512 k x 2B (swizzled)

// dynamic smem layout
#define SM_WCACHE 0                         // float4[128] = 2048
#define SM_OCACHE 2048                      // int4[128]   = 2048
#define SM_S      4096
#define SM_WBUF   (4096 + S_BYTES)          // 2 x 32768
#define SMEM_FUSED (SM_WBUF + 2 * W_CHUNK_BYTES)   // 200704 B

// ---------------- scratch (device globals: no allocation allowed) -------------
__device__ __half g_imgT[BSZ * IMH * IMW * C_IMG];          // (B,H,W,C) fp16, ~63 MB
__device__ __align__(16) char g_Wbf16[C_PT * C_IMG * 2];    // bf16 W, chunked+swizzled
__device__ float  g_M[BSZ * 12];
__device__ float4 g_w[NPTS];
__device__ int4   g_off[NPTS];

// ---------------- helpers ------------------------------------------------------
__device__ __forceinline__ uint32_t smem_u32(const void* p) {
    uint32_t a;
    asm("{ .reg .u64 t; cvta.to.shared.u64 t, %1; cvt.u32.u64 %0, t; }"
        : "=r"(a) : "l"(p));
    return a;
}

#define LDSM_X4(r0, r1, r2, r3, addr) \
    asm volatile("ldmatrix.sync.aligned.m8n8.x4.shared.b16 {%0,%1,%2,%3}, [%4];" \
                 : "=r"(r0), "=r"(r1), "=r"(r2), "=r"(r3) : "r"(addr))

__device__ __forceinline__ void mma_bf16(float* d, const uint32_t* a,
                                         uint32_t b0, uint32_t b1) {
    asm volatile(
        "mma.sync.aligned.m16n8k16.row.col.f32.bf16.bf16.f32 "
        "{%0,%1,%2,%3}, {%4,%5,%6,%7}, {%8,%9}, {%0,%1,%2,%3};"
        : "+f"(d[0]), "+f"(d[1]), "+f"(d[2]), "+f"(d[3])
        : "r"(a[0]), "r"(a[1]), "r"(a[2]), "r"(a[3]), "r"(b0), "r"(b1));
}

#define CP_ASYNC16(dst, src) \
    asm volatile("cp.async.cg.shared.global [%0], [%1], 16;" \
                 :: "r"(dst), "l"(src) : "memory")
#define CP_COMMIT() asm volatile("cp.async.commit_group;" ::: "memory")
#define CP_WAIT_ALL() asm volatile("cp.async.wait_group 0;" ::: "memory")

// ================== kernel 0: combined projection matrices ===================
__global__ void build_mats_kernel(const float* __restrict__ P2,
                                  const float* __restrict__ R0,
                                  const float* __restrict__ Tr) {
    int b = threadIdx.x;
    if (b >= BSZ) return;
    float A[16];
    for (int i = 0; i < 4; ++i)
        for (int j = 0; j < 4; ++j) {
            float s = 0.f;
            for (int k = 0; k < 4; ++k)
                s += R0[b*16 + i*4 + k] * Tr[b*16 + k*4 + j];
            A[i*4 + j] = s;
        }
    for (int i = 0; i < 3; ++i)
        for (int j = 0; j < 4; ++j) {
            float s = 0.f;
            for (int k = 0; k < 4; ++k)
                s += P2[b*12 + i*4 + k] * A[k*4 + j];
            g_M[b*12 + i*4 + j] = s;
        }
}

// ================== kernel 1: transpose img (B,C,H,W)->(B,H,W,C) fp16 ========
__global__ void transpose_img_kernel(const float* __restrict__ img) {
    __shared__ float tile[32][33];
    int bz = blockIdx.z;
    int b = bz / IMH, y = bz % IMH;
    int x0 = blockIdx.x * 32, c0 = blockIdx.y * 32;
    int tx = threadIdx.x, ty = threadIdx.y;
    #pragma unroll
    for (int j = 0; j < 4; ++j) {
        int c = c0 + ty + j * 8;
        tile[ty + j * 8][tx] =
            img[((size_t)(b * C_IMG + c) * IMH + y) * IMW + x0 + tx];
    }
    __syncthreads();
    #pragma unroll
    for (int j = 0; j < 4; ++j) {
        int x = x0 + ty + j * 8;
        g_imgT[((size_t)((b * IMH + y) * IMW + x)) * C_IMG + c0 + tx] =
            __float2half(tile[tx][ty + j * 8]);
    }
}

// ================== kernel 2: per-point projection ============================
__global__ void project_kernel(const float* __restrict__ centers,
                               const int* __restrict__ bidx) {
    int tid = blockIdx.x * blockDim.x + threadIdx.x;
    if (tid >= NPTS) return;
    int b = bidx[tid];
    const float* M = g_M + b * 12;
    float x = centers[tid * 3 + 0];
    float y = centers[tid * 3 + 1];
    float z = centers[tid * 3 + 2];
    float u  = M[0] * x + M[1] * y + M[2]  * z + M[3];
    float v  = M[4] * x + M[5] * y + M[6]  * z + M[7];
    float zc = M[8] * x + M[9] * y + M[10] * z + M[11];
    float depth = fmaxf(zc, 1e-5f);
    float uu = u / depth;
    float vv = v / depth;
    bool valid = (zc > 0.f) && (uu >= 0.f) && (uu < (float)IMW) &&
                 (vv >= 0.f) && (vv < (float)IMH);
    float x0f = floorf(uu), y0f = floorf(vv);
    float wx1 = uu - x0f, wx0 = 1.f - wx1;
    float wy1 = vv - y0f, wy0 = 1.f - wy1;
    int xi0 = (int)x0f, yi0 = (int)y0f;

    int   xs[4] = {xi0, xi0 + 1, xi0, xi0 + 1};
    int   ys[4] = {yi0, yi0, yi0 + 1, yi0 + 1};
    float ws[4] = {wx0 * wy0, wx1 * wy0, wx0 * wy1, wx1 * wy1};
    float wo[4];
    int   oo[4];
    #pragma unroll
    for (int j = 0; j < 4; ++j) {
        bool inb = (xs[j] >= 0) && (xs[j] <= IMW - 1) &&
                   (ys[j] >= 0) && (ys[j] <= IMH - 1);
        int xc = min(max(xs[j], 0), IMW - 1);
        int yc = min(max(ys[j], 0), IMH - 1);
        oo[j] = ((b * IMH + yc) * IMW + xc) * C_IMG;
        wo[j] = (valid && inb) ? ws[j] : 0.f;   // select, never multiply (NaN safety)
    }
    g_w[tid]   = make_float4(wo[0], wo[1], wo[2], wo[3]);
    g_off[tid] = make_int4(oo[0], oo[1], oo[2], oo[3]);
}

// ================== kernel 3: align_w fp32 -> bf16, chunked + swizzled ========
// layout: chunk c (32KB): n-row (128B = 8 16B-blocks), block kb stored at
//         byte = c*32768 + n*128 + ((kb ^ (n&7)) << 4)
__global__ void prep_w_kernel(const float* __restrict__ aw) {
    int idx = blockIdx.x * 256 + threadIdx.x;   // 16384 16B-blocks
    int n   = idx >> 6;          // out channel 0..255
    int kbg = idx & 63;          // global 16B k-block (8 bf16)
    int c   = kbg >> 3;
    int kb  = kbg & 7;
    const float4* src = (const float4*)&aw[(size_t)n * C_IMG + kbg * 8];
    float4 v0 = src[0];
    float4 v1 = src[1];
    uint32_t u[4];
    __nv_bfloat162 t0 = __float22bfloat162_rn(make_float2(v0.x, v0.y));
    __nv_bfloat162 t1 = __float22bfloat162_rn(make_float2(v0.z, v0.w));
    __nv_bfloat162 t2 = __float22bfloat162_rn(make_float2(v1.x, v1.y));
    __nv_bfloat162 t3 = __float22bfloat162_rn(make_float2(v1.z, v1.w));
    u[0] = *(uint32_t*)&t0; u[1] = *(uint32_t*)&t1;
    u[2] = *(uint32_t*)&t2; u[3] = *(uint32_t*)&t3;
    *(int4*)(g_Wbf16 + c * W_CHUNK_BYTES + n * 128 + ((kb ^ (n & 7)) << 4)) =
        *(int4*)u;
}

// ================== kernel 4: fused gather + HMMA GEMM + residual =============
// 512 threads = 16 warps, warp grid 4(M) x 4(N). Warp tile 32x64.
__global__ void __launch_bounds__(512, 1)
fuse_kernel(const float* __restrict__ point_feat,
            const float* __restrict__ align_b,
            float* __restrict__ out) {
    extern __shared__ char sm[];
    uint32_t smb = smem_u32(sm);
    float4* wcache = (float4*)(sm + SM_WCACHE);
    int4*   ocache = (int4*)(sm + SM_OCACHE);

    const int t    = threadIdx.x;
    const int lane = t & 31;
    const int warp = t >> 5;
    const int p0   = blockIdx.x * TM;

    // point weights/offsets -> smem
    if (t < TM) {
        int p = p0 + t;
        float4 w = make_float4(0.f, 0.f, 0.f, 0.f);
        int4   o = make_int4(0, 0, 0, 0);
        if (p < NPTS) { w = g_w[p]; o = g_off[p]; }
        wcache[t] = w;
        ocache[t] = o;
    }

    // prefetch W chunk 0 (overlaps gather)
    {
        const char* src = g_Wbf16;
        uint32_t dst = smb + SM_WBUF;
        #pragma unroll
        for (int j = 0; j < 4; ++j)
            CP_ASYNC16(dst + (t + j * 512) * 16, src + (size_t)(t + j * 512) * 16);
        CP_COMMIT();
    }
    __syncthreads();

    // ---- gather: S[p][k] bf16, swizzled. thread handles channel pair cp for
    //      64 points (threads 0-255: points 0-63, 256-511: points 64-127).
    const __half2* img2 = (const __half2*)g_imgT;
    const int cp    = t & 255;
    const int pbase = (t >> 8) * 64;
    const uint32_t sbase = smb + SM_S;
    const uint32_t wordoff = (cp & 3) * 4;
    #pragma unroll 4
    for (int q = 0; q < 64; ++q) {
        int p = pbase + q;
        float4 w = wcache[p];
        int4   o = ocache[p];
        float2 f0 = __half22float2(img2[(o.x >> 1) + cp]);
        float2 f1 = __half22float2(img2[(o.y >> 1) + cp]);
        float2 f2 = __half22float2(img2[(o.z >> 1) + cp]);
        float2 f3 = __half22float2(img2[(o.w >> 1) + cp]);
        float se = w.x * f0.x + w.y * f1.x + w.z * f2.x + w.w * f3.x;
        float so = w.x * f0.y + w.y * f1.y + w.z * f2.y + w.w * f3.y;
        __nv_bfloat162 b2 = __float22bfloat162_rn(make_float2(se, so));
        uint32_t addr = sbase + p * 1024 +
                        ((((unsigned)cp >> 2) ^ (p & 7)) << 4) + wordoff;
        asm volatile("st.shared.b32 [%0], %1;" :: "r"(addr), "r"(*(uint32_t*)&b2));
    }
    CP_WAIT_ALL();      // W chunk 0 resident
    __syncthreads();    // S tile complete

    // ---- HMMA mainloop --------------------------------------------------------
    const int wm = warp & 3;    // M group (32 rows)
    const int wn = warp >> 2;   // N group (64 cols)
    float acc[2][8][4];
    #pragma unroll
    for (int i = 0; i < 2; ++i)
        #pragma unroll
        for (int j = 0; j < 8; ++j)
            #pragma unroll
            for (int r = 0; r < 4; ++r) acc[i][j][r] = 0.f;

    // per-lane invariant address parts
    const int arow0 = wm * 32 + (lane & 15);
    const int ahalf = lane >> 4;
    const int brow  = wn * 64 + (lane >> 4) * 8 + (lane & 7);
    const int bhalf = (lane >> 3) & 1;

    for (int c = 0; c < NCHUNK; ++c) {
        if (c + 1 < NCHUNK) {
            const char* src = g_Wbf16 + (size_t)(c + 1) * W_CHUNK_BYTES;
            uint32_t dst = smb + SM_WBUF + ((c + 1) & 1) * W_CHUNK_BYTES;
            #pragma unroll
            for (int j = 0; j < 4; ++j)
                CP_ASYNC16(dst + (t + j * 512) * 16, src + (size_t)(t + j * 512) * 16);
            CP_COMMIT();
        }
        const uint32_t wbuf = smb + SM_WBUF + (c & 1) * W_CHUNK_BYTES;

        #pragma unroll
        for (int ks = 0; ks < 4; ++ks) {
            uint32_t a[2][4];
            #pragma unroll
            for (int i = 0; i < 2; ++i) {
                int row  = arow0 + i * 16;
                int kblk = (c * 8 + ks * 2 + ahalf) ^ (row & 7);
                uint32_t addr = sbase + row * 1024 + (kblk << 4);
                LDSM_X4(a[i][0], a[i][1], a[i][2], a[i][3], addr);
            }
            #pragma unroll
            for (int jj = 0; jj < 4; ++jj) {
                uint32_t b0, b1, b2, b3;
                int nrow = brow + jj * 16;
                int kblk = (ks * 2 + bhalf) ^ (nrow & 7);
                uint32_t addr = wbuf + nrow * 128 + (kblk << 4);
                LDSM_X4(b0, b1, b2, b3, addr);
                mma_bf16(acc[0][2 * jj],     a[0], b0, b1);
                mma_bf16(acc[0][2 * jj + 1], a[0], b2, b3);
                mma_bf16(acc[1][2 * jj],     a[1], b0, b1);
                mma_bf16(acc[1][2 * jj + 1], a[1], b2, b3);
            }
        }
        CP_WAIT_ALL();
        __syncthreads();
    }

    // ---- epilogue: out = point_feat + bias + acc -------------------------------
    const int cbase = wn * 64 + (lane & 3) * 2;
    float2 bias[8];
    #pragma unroll
    for (int j = 0; j < 8; ++j)
        bias[j] = *(const float2*)&align_b[cbase + j * 8];

    const int rbase = p0 + wm * 32 + (lane >> 2);
    #pragma unroll
    for (int i = 0; i < 2; ++i) {
        #pragma unroll
        for (int half = 0; half < 2; ++half) {
            int row = rbase + i * 16 + half * 8;
            if (row < NPTS) {
                #pragma unroll
                for (int j = 0; j < 8; ++j) {
                    int col = cbase + j * 8;
                    float2 a = *(const float2*)&point_feat[(size_t)row * C_PT + col];
                    float2 o;
                    o.x = a.x + bias[j].x + acc[i][j][half * 2 + 0];
                    o.y = a.y + bias[j].y + acc[i][j][half * 2 + 1];
                    *(float2*)&out[(size_t)row * C_PT + col] = o;
                }
            }
        }
    }
}

// ================== launcher ==================================================
extern "C" void kernel_launch(void* const* d_in, const int* in_sizes, int n_in,
                              void* d_out, int out_size) {
    const float* point_feat = (const float*)d_in[0];
    const float* centers    = (const float*)d_in[1];
    const float* img        = (const float*)d_in[2];
    const float* P2         = (const float*)d_in[3];
    const float* R0         = (const float*)d_in[4];
    const float* Tr         = (const float*)d_in[5];
    const float* align_w    = (const float*)d_in[6];
    const float* align_b    = (const float*)d_in[7];
    const int*   bidx       = (const int*)d_in[8];
    float* out = (float*)d_out;

    build_mats_kernel<<<1, 32>>>(P2, R0, Tr);
    transpose_img_kernel<<<dim3(IMW / 32, C_IMG / 32, BSZ * IMH), dim3(32, 8)>>>(img);
    project_kernel<<<(NPTS + 255) / 256, 256>>>(centers, bidx);
    prep_w_kernel<<<64, 256>>>(align_w);

    cudaFuncSetAttribute(fuse_kernel,
                         cudaFuncAttributeMaxDynamicSharedMemorySize, SMEM_FUSED);
    fuse_kernel<<<(NPTS + TM - 1) / TM, 512, SMEM_FUSED>>>(point_feat, align_b, out);
}

// round 4
// speedup vs baseline: 4.3121x; 1.3500x over previous
#include <cuda_runtime.h>
#include <cuda_fp16.h>
#include <cuda_bf16.h>
#include <cstdint>

// Problem constants (fixed by the reference)
#define NPTS   100000
#define C_IMG  512
#define C_PT   256
#define BSZ    8
#define IMH    48
#define IMW    160

#define TM     64                // points per CTA (MMA M)
#define NCHUNK 16                // K chunks of 32
#define W_CHUNK_BYTES 16384      // 256 n-rows x 32 k x 2B (swizzled, 64B rows)
#define S_BYTES (TM * 1024)      // 64 rows x 512 k x 2B (swizzled, 1KB rows)

// dynamic smem layout
#define SM_WCACHE 0                         // float4[64] = 1024
#define SM_OCACHE 1024                      // int4[64]   = 1024
#define SM_S      2048
#define SM_WBUF   (2048 + S_BYTES)          // 2 x 16384
#define SMEM_FUSED (SM_WBUF + 2 * W_CHUNK_BYTES)   // 100352 B -> 2 CTAs/SM

// ---------------- scratch (device globals: no allocation allowed) -------------
__device__ __half g_imgT[BSZ * IMH * IMW * C_IMG];          // (B,H,W,C) fp16, ~63 MB
__device__ __align__(16) char g_Wbf16[C_PT * C_IMG * 2];    // bf16 W, chunked+swizzled
__device__ float  g_M[BSZ * 12];
__device__ float4 g_w[NPTS];
__device__ int4   g_off[NPTS];

// ---------------- helpers ------------------------------------------------------
__device__ __forceinline__ uint32_t smem_u32(const void* p) {
    uint32_t a;
    asm("{ .reg .u64 t; cvta.to.shared.u64 t, %1; cvt.u32.u64 %0, t; }"
        : "=r"(a) : "l"(p));
    return a;
}

#define LDSM_X4(r0, r1, r2, r3, addr) \
    asm volatile("ldmatrix.sync.aligned.m8n8.x4.shared.b16 {%0,%1,%2,%3}, [%4];" \
                 : "=r"(r0), "=r"(r1), "=r"(r2), "=r"(r3) : "r"(addr))

__device__ __forceinline__ void mma_bf16(float* d, const uint32_t* a,
                                         uint32_t b0, uint32_t b1) {
    asm volatile(
        "mma.sync.aligned.m16n8k16.row.col.f32.bf16.bf16.f32 "
        "{%0,%1,%2,%3}, {%4,%5,%6,%7}, {%8,%9}, {%0,%1,%2,%3};"
        : "+f"(d[0]), "+f"(d[1]), "+f"(d[2]), "+f"(d[3])
        : "r"(a[0]), "r"(a[1]), "r"(a[2]), "r"(a[3]), "r"(b0), "r"(b1));
}

#define CP_ASYNC16(dst, src) \
    asm volatile("cp.async.cg.shared.global [%0], [%1], 16;" \
                 :: "r"(dst), "l"(src) : "memory")
#define CP_COMMIT() asm volatile("cp.async.commit_group;" ::: "memory")
#define CP_WAIT_ALL() asm volatile("cp.async.wait_group 0;" ::: "memory")

// ================== kernel 0: combined projection matrices ===================
__global__ void build_mats_kernel(const float* __restrict__ P2,
                                  const float* __restrict__ R0,
                                  const float* __restrict__ Tr) {
    int b = threadIdx.x;
    if (b >= BSZ) return;
    float A[16];
    for (int i = 0; i < 4; ++i)
        for (int j = 0; j < 4; ++j) {
            float s = 0.f;
            for (int k = 0; k < 4; ++k)
                s += R0[b*16 + i*4 + k] * Tr[b*16 + k*4 + j];
            A[i*4 + j] = s;
        }
    for (int i = 0; i < 3; ++i)
        for (int j = 0; j < 4; ++j) {
            float s = 0.f;
            for (int k = 0; k < 4; ++k)
                s += P2[b*12 + i*4 + k] * A[k*4 + j];
            g_M[b*12 + i*4 + j] = s;
        }
}

// ================== kernel 1: transpose img (B,C,H,W)->(B,H,W,C) fp16 ========
__global__ void transpose_img_kernel(const float* __restrict__ img) {
    __shared__ float tile[32][33];
    int bz = blockIdx.z;
    int b = bz / IMH, y = bz % IMH;
    int x0 = blockIdx.x * 32, c0 = blockIdx.y * 32;
    int tx = threadIdx.x, ty = threadIdx.y;
    #pragma unroll
    for (int j = 0; j < 4; ++j) {
        int c = c0 + ty + j * 8;
        tile[ty + j * 8][tx] =
            img[((size_t)(b * C_IMG + c) * IMH + y) * IMW + x0 + tx];
    }
    __syncthreads();
    #pragma unroll
    for (int j = 0; j < 4; ++j) {
        int x = x0 + ty + j * 8;
        g_imgT[((size_t)((b * IMH + y) * IMW + x)) * C_IMG + c0 + tx] =
            __float2half(tile[tx][ty + j * 8]);
    }
}

// ================== kernel 2: per-point projection ============================
__global__ void project_kernel(const float* __restrict__ centers,
                               const int* __restrict__ bidx) {
    int tid = blockIdx.x * blockDim.x + threadIdx.x;
    if (tid >= NPTS) return;
    int b = bidx[tid];
    const float* M = g_M + b * 12;
    float x = centers[tid * 3 + 0];
    float y = centers[tid * 3 + 1];
    float z = centers[tid * 3 + 2];
    float u  = M[0] * x + M[1] * y + M[2]  * z + M[3];
    float v  = M[4] * x + M[5] * y + M[6]  * z + M[7];
    float zc = M[8] * x + M[9] * y + M[10] * z + M[11];
    float depth = fmaxf(zc, 1e-5f);
    float uu = u / depth;
    float vv = v / depth;
    bool valid = (zc > 0.f) && (uu >= 0.f) && (uu < (float)IMW) &&
                 (vv >= 0.f) && (vv < (float)IMH);
    float x0f = floorf(uu), y0f = floorf(vv);
    float wx1 = uu - x0f, wx0 = 1.f - wx1;
    float wy1 = vv - y0f, wy0 = 1.f - wy1;
    int xi0 = (int)x0f, yi0 = (int)y0f;

    int   xs[4] = {xi0, xi0 + 1, xi0, xi0 + 1};
    int   ys[4] = {yi0, yi0, yi0 + 1, yi0 + 1};
    float ws[4] = {wx0 * wy0, wx1 * wy0, wx0 * wy1, wx1 * wy1};
    float wo[4];
    int   oo[4];
    #pragma unroll
    for (int j = 0; j < 4; ++j) {
        bool inb = (xs[j] >= 0) && (xs[j] <= IMW - 1) &&
                   (ys[j] >= 0) && (ys[j] <= IMH - 1);
        int xc = min(max(xs[j], 0), IMW - 1);
        int yc = min(max(ys[j], 0), IMH - 1);
        oo[j] = ((b * IMH + yc) * IMW + xc) * C_IMG;
        wo[j] = (valid && inb) ? ws[j] : 0.f;   // select, never multiply (NaN safety)
    }
    g_w[tid]   = make_float4(wo[0], wo[1], wo[2], wo[3]);
    g_off[tid] = make_int4(oo[0], oo[1], oo[2], oo[3]);
}

// ================== kernel 3: align_w fp32 -> bf16, chunked + swizzled ========
// layout: chunk c (16KB, K=32): n-row (64B = 4 16B-blocks), block kb stored at
//         byte = c*16384 + n*64 + ((kb ^ ((n>>1)&3)) << 4)
__global__ void prep_w_kernel(const float* __restrict__ aw) {
    int idx = blockIdx.x * 256 + threadIdx.x;   // 16384 16B-blocks
    int n   = idx >> 6;          // out channel 0..255
    int kbg = idx & 63;          // global 16B k-block (8 bf16)
    int c   = kbg >> 2;          // chunk 0..15
    int kb  = kbg & 3;           // block within chunk
    const float4* src = (const float4*)&aw[(size_t)n * C_IMG + kbg * 8];
    float4 v0 = src[0];
    float4 v1 = src[1];
    uint32_t u[4];
    __nv_bfloat162 t0 = __float22bfloat162_rn(make_float2(v0.x, v0.y));
    __nv_bfloat162 t1 = __float22bfloat162_rn(make_float2(v0.z, v0.w));
    __nv_bfloat162 t2 = __float22bfloat162_rn(make_float2(v1.x, v1.y));
    __nv_bfloat162 t3 = __float22bfloat162_rn(make_float2(v1.z, v1.w));
    u[0] = *(uint32_t*)&t0; u[1] = *(uint32_t*)&t1;
    u[2] = *(uint32_t*)&t2; u[3] = *(uint32_t*)&t3;
    *(int4*)(g_Wbf16 + c * W_CHUNK_BYTES + n * 64 + ((kb ^ ((n >> 1) & 3)) << 4)) =
        *(int4*)u;
}

// ================== kernel 4: fused gather + HMMA GEMM + residual =============
// 512 threads = 16 warps, warp grid 2(M) x 8(N). Warp tile 32x32.
// 98KB smem -> 2 CTAs/SM: gather/MMA/epilogue of co-resident CTAs overlap.
__global__ void __launch_bounds__(512, 2)
fuse_kernel(const float* __restrict__ point_feat,
            const float* __restrict__ align_b,
            float* __restrict__ out) {
    extern __shared__ char sm[];
    uint32_t smb = smem_u32(sm);
    float4* wcache = (float4*)(sm + SM_WCACHE);
    int4*   ocache = (int4*)(sm + SM_OCACHE);

    const int t    = threadIdx.x;
    const int lane = t & 31;
    const int warp = t >> 5;
    const int p0   = blockIdx.x * TM;

    // point weights/offsets -> smem
    if (t < TM) {
        int p = p0 + t;
        float4 w = make_float4(0.f, 0.f, 0.f, 0.f);
        int4   o = make_int4(0, 0, 0, 0);
        if (p < NPTS) { w = g_w[p]; o = g_off[p]; }
        wcache[t] = w;
        ocache[t] = o;
    }

    // prefetch W chunk 0 (overlaps gather)
    {
        const char* src = g_Wbf16;
        uint32_t dst = smb + SM_WBUF;
        #pragma unroll
        for (int j = 0; j < 2; ++j)
            CP_ASYNC16(dst + (t + j * 512) * 16, src + (size_t)(t + j * 512) * 16);
        CP_COMMIT();
    }
    __syncthreads();

    // ---- gather: S[p][k] bf16, swizzled. thread handles channel pair cp for
    //      32 points (threads 0-255: points 0-31, 256-511: points 32-63).
    const __half2* img2 = (const __half2*)g_imgT;
    const int cp    = t & 255;
    const int pbase = (t >> 8) * 32;
    const uint32_t sbase = smb + SM_S;
    const uint32_t wordoff = (cp & 3) * 4;
    #pragma unroll 4
    for (int q = 0; q < 32; ++q) {
        int p = pbase + q;
        float4 w = wcache[p];
        int4   o = ocache[p];
        float2 f0 = __half22float2(img2[(o.x >> 1) + cp]);
        float2 f1 = __half22float2(img2[(o.y >> 1) + cp]);
        float2 f2 = __half22float2(img2[(o.z >> 1) + cp]);
        float2 f3 = __half22float2(img2[(o.w >> 1) + cp]);
        float se = w.x * f0.x + w.y * f1.x + w.z * f2.x + w.w * f3.x;
        float so = w.x * f0.y + w.y * f1.y + w.z * f2.y + w.w * f3.y;
        __nv_bfloat162 b2 = __float22bfloat162_rn(make_float2(se, so));
        uint32_t addr = sbase + p * 1024 +
                        ((((unsigned)cp >> 2) ^ (p & 7)) << 4) + wordoff;
        asm volatile("st.shared.b32 [%0], %1;" :: "r"(addr), "r"(*(uint32_t*)&b2));
    }
    CP_WAIT_ALL();      // W chunk 0 resident
    __syncthreads();    // S tile complete

    // ---- HMMA mainloop --------------------------------------------------------
    const int wm = warp & 1;    // M group (32 rows)
    const int wn = warp >> 1;   // N group (32 cols)
    float acc[2][4][4];
    #pragma unroll
    for (int i = 0; i < 2; ++i)
        #pragma unroll
        for (int j = 0; j < 4; ++j)
            #pragma unroll
            for (int r = 0; r < 4; ++r) acc[i][j][r] = 0.f;

    // per-lane invariant address parts
    const int arow0 = wm * 32 + (lane & 15);
    const int ahalf = lane >> 4;
    const int brow  = wn * 32 + (lane >> 4) * 8 + (lane & 7);
    const int bhalf = (lane >> 3) & 1;

    for (int c = 0; c < NCHUNK; ++c) {
        if (c + 1 < NCHUNK) {
            const char* src = g_Wbf16 + (size_t)(c + 1) * W_CHUNK_BYTES;
            uint32_t dst = smb + SM_WBUF + ((c + 1) & 1) * W_CHUNK_BYTES;
            #pragma unroll
            for (int j = 0; j < 2; ++j)
                CP_ASYNC16(dst + (t + j * 512) * 16, src + (size_t)(t + j * 512) * 16);
            CP_COMMIT();
        }
        const uint32_t wbuf = smb + SM_WBUF + (c & 1) * W_CHUNK_BYTES;

        #pragma unroll
        for (int ks = 0; ks < 2; ++ks) {
            uint32_t a[2][4];
            #pragma unroll
            for (int i = 0; i < 2; ++i) {
                int row  = arow0 + i * 16;
                int kblk = (c * 4 + ks * 2 + ahalf) ^ (row & 7);
                uint32_t addr = sbase + row * 1024 + (kblk << 4);
                LDSM_X4(a[i][0], a[i][1], a[i][2], a[i][3], addr);
            }
            #pragma unroll
            for (int jj = 0; jj < 2; ++jj) {
                uint32_t b0, b1, b2, b3;
                int nrow = brow + jj * 16;
                int kb   = (ks * 2 + bhalf) ^ ((nrow >> 1) & 3);
                uint32_t addr = wbuf + nrow * 64 + (kb << 4);
                LDSM_X4(b0, b1, b2, b3, addr);
                mma_bf16(acc[0][2 * jj],     a[0], b0, b1);
                mma_bf16(acc[0][2 * jj + 1], a[0], b2, b3);
                mma_bf16(acc[1][2 * jj],     a[1], b0, b1);
                mma_bf16(acc[1][2 * jj + 1], a[1], b2, b3);
            }
        }
        CP_WAIT_ALL();
        __syncthreads();
    }

    // ---- epilogue: out = point_feat + bias + acc -------------------------------
    const int cbase = wn * 32 + (lane & 3) * 2;
    float2 bias[4];
    #pragma unroll
    for (int j = 0; j < 4; ++j)
        bias[j] = *(const float2*)&align_b[cbase + j * 8];

    const int rbase = p0 + wm * 32 + (lane >> 2);
    #pragma unroll
    for (int i = 0; i < 2; ++i) {
        #pragma unroll
        for (int half = 0; half < 2; ++half) {
            int row = rbase + i * 16 + half * 8;
            if (row < NPTS) {
                #pragma unroll
                for (int j = 0; j < 4; ++j) {
                    int col = cbase + j * 8;
                    float2 a = *(const float2*)&point_feat[(size_t)row * C_PT + col];
                    float2 o;
                    o.x = a.x + bias[j].x + acc[i][j][half * 2 + 0];
                    o.y = a.y + bias[j].y + acc[i][j][half * 2 + 1];
                    *(float2*)&out[(size_t)row * C_PT + col] = o;
                }
            }
        }
    }
}

// ================== launcher ==================================================
extern "C" void kernel_launch(void* const* d_in, const int* in_sizes, int n_in,
                              void* d_out, int out_size) {
    const float* point_feat = (const float*)d_in[0];
    const float* centers    = (const float*)d_in[1];
    const float* img        = (const float*)d_in[2];
    const float* P2         = (const float*)d_in[3];
    const float* R0         = (const float*)d_in[4];
    const float* Tr         = (const float*)d_in[5];
    const float* align_w    = (const float*)d_in[6];
    const float* align_b    = (const float*)d_in[7];
    const int*   bidx       = (const int*)d_in[8];
    float* out = (float*)d_out;

    build_mats_kernel<<<1, 32>>>(P2, R0, Tr);
    transpose_img_kernel<<<dim3(IMW / 32, C_IMG / 32, BSZ * IMH), dim3(32, 8)>>>(img);
    project_kernel<<<(NPTS + 255) / 256, 256>>>(centers, bidx);
    prep_w_kernel<<<64, 256>>>(align_w);

    cudaFuncSetAttribute(fuse_kernel,
                         cudaFuncAttributeMaxDynamicSharedMemorySize, SMEM_FUSED);
    fuse_kernel<<<(NPTS + TM - 1) / TM, 512, SMEM_FUSED>>>(point_feat, align_b, out);
}